// round 8
// baseline (speedup 1.0000x reference)
#include <cuda_runtime.h>
#include <cuda_bf16.h>
#include <math.h>
#include <stdint.h>

// Problem dims
#define BATCH 32
#define SEQ   128
#define EDIM  512
#define HDIM  512
#define VDIM  32000
#define G3H   1536   // 3*HDIM
#define KTOT  1536   // expanded split-3 K

// ---------------- scratch (device globals: allocation-free) ----------------
__device__ __align__(256) float g_xg[SEQ * BATCH * G3H];   // [s][b][3H]
__device__ __align__(256) float g_hs[SEQ * BATCH * HDIM];  // [s][b][H]
__device__ __align__(256) float g_h [BATCH * HDIM];
__device__ int g_arrive;
__device__ int g_exit;

// expanded bf16 split-3 operands  (A' = [hi|hi|lo], B' = [hi|lo|hi])
__device__ __align__(256) __nv_bfloat16 g_axg[SEQ * BATCH * KTOT];
__device__ __align__(256) __nv_bfloat16 g_bxg[G3H * KTOT];
__device__ __align__(256) __nv_bfloat16 g_a  [SEQ * BATCH * KTOT];
__device__ __align__(256) __nv_bfloat16 g_b  [VDIM * KTOT];

// ===================== PTX helpers (plain sm_80+ PTX) =======================
__device__ __forceinline__ uint32_t smem_u32(const void* p) {
    uint32_t a;
    asm("{ .reg .u64 t; cvta.to.shared.u64 t, %1; cvt.u32.u64 %0, t; }"
        : "=r"(a) : "l"(p));
    return a;
}
#define CP_ASYNC_16(dst, src) \
    asm volatile("cp.async.cg.shared.global [%0], [%1], 16;" \
                 :: "r"(dst), "l"(src) : "memory")
#define CP_COMMIT() asm volatile("cp.async.commit_group;" ::: "memory")
#define CP_WAIT1()  asm volatile("cp.async.wait_group 1;" ::: "memory")

__device__ __forceinline__ void ldsm_x4(uint32_t* r, uint32_t addr) {
    asm volatile("ldmatrix.sync.aligned.m8n8.x4.shared.b16 {%0,%1,%2,%3}, [%4];"
                 : "=r"(r[0]), "=r"(r[1]), "=r"(r[2]), "=r"(r[3]) : "r"(addr));
}
__device__ __forceinline__ void mma_16816(float* c, const uint32_t* a,
                                          const uint32_t* b) {
    asm volatile(
        "mma.sync.aligned.m16n8k16.row.col.f32.bf16.bf16.f32 "
        "{%0,%1,%2,%3}, {%4,%5,%6,%7}, {%8,%9}, {%0,%1,%2,%3};"
        : "+f"(c[0]), "+f"(c[1]), "+f"(c[2]), "+f"(c[3])
        : "r"(a[0]), "r"(a[1]), "r"(a[2]), "r"(a[3]), "r"(b[0]), "r"(b[1]));
}

// ---------------- split/expand kernels --------------------------------------
// src fp32 [rows][512] -> dst bf16 [rows][1536]
// ISB=0 (A side): segs [hi, hi, lo];  ISB=1 (B side): segs [hi, lo, hi]
// REMAP=1: src row = (r&31)*SEQ + (r>>5)
template <int REMAP, int ISB>
__global__ __launch_bounds__(256) void split_expand_kernel(
    const float* __restrict__ src, __nv_bfloat16* __restrict__ dst, int rows)
{
    const int i = blockIdx.x * blockDim.x + threadIdx.x;
    if (i >= rows * 128) return;
    const int r = i >> 7;
    const int c4 = (i & 127) * 4;
    long srow;
    if (REMAP) srow = (long)((r & 31) * SEQ + (r >> 5)) * 512;
    else       srow = (long)r * 512;
    float4 v = *(const float4*)(src + srow + c4);
    __nv_bfloat16 h0 = __float2bfloat16(v.x), h1 = __float2bfloat16(v.y);
    __nv_bfloat16 h2 = __float2bfloat16(v.z), h3 = __float2bfloat16(v.w);
    __nv_bfloat16 l0 = __float2bfloat16(v.x - __bfloat162float(h0));
    __nv_bfloat16 l1 = __float2bfloat16(v.y - __bfloat162float(h1));
    __nv_bfloat16 l2 = __float2bfloat16(v.z - __bfloat162float(h2));
    __nv_bfloat16 l3 = __float2bfloat16(v.w - __bfloat162float(h3));
    __nv_bfloat162 hA(h0, h1), hB(h2, h3);
    __nv_bfloat162 lA(l0, l1), lB(l2, l3);
    __nv_bfloat16* d = dst + (long)r * KTOT + c4;
    *(__nv_bfloat162*)(d + 0) = hA; *(__nv_bfloat162*)(d + 2) = hB;
    if (ISB) {
        *(__nv_bfloat162*)(d + 512)  = lA; *(__nv_bfloat162*)(d + 514)  = lB;
        *(__nv_bfloat162*)(d + 1024) = hA; *(__nv_bfloat162*)(d + 1026) = hB;
    } else {
        *(__nv_bfloat162*)(d + 512)  = hA; *(__nv_bfloat162*)(d + 514)  = hB;
        *(__nv_bfloat162*)(d + 1024) = lA; *(__nv_bfloat162*)(d + 1026) = lB;
    }
}

// ---------------- bf16 HMMA GEMM: C[M,N] = A'[M,1536] * B'[N,1536]^T --------
// CTA tile 128(M) x 256(N), 8 warps (2m x 4n), warp tile 64x64.
// K-step 64 (128B rows, XOR swizzle), 3-stage cp.async, 256 threads.
// Fragment double-buffering: kk+1's LDSM issued before kk's MMAs so the
// tensor pipe stays busy through LDSM latency.
// MODE 0: +bias, C row = m.   MODE 1: no bias, C row = (m&31)*SEQ+(m>>5).
#define STGB ((128 + 256) * 128)       // 49152 per stage: A(128 rows) then B(256)
#define NSTG 3
#define SMEM_MMA (NSTG * STGB)         // 147456

template <int MODE>
__global__ __launch_bounds__(256, 1) void mma_gemm_kernel(
    const __nv_bfloat16* __restrict__ A, const __nv_bfloat16* __restrict__ B,
    const float* __restrict__ bias, float* __restrict__ C, int N)
{
    extern __shared__ char smem[];
    const uint32_t sb = smem_u32(smem);
    const int tid  = threadIdx.x;
    const int wid  = tid >> 5, lane = tid & 31;
    const int m0   = blockIdx.x * 128;
    const int n0   = blockIdx.y * 256;
    const int wm   = wid & 1;            // 2 warps along m (64 each)
    const int wn   = wid >> 1;           // 4 warps along n (64 each)

    // ---- cp.async mapping: row = r8 (+32*i), col16 = c7
    const int r8 = tid >> 3;             // 0..31
    const int c7 = tid & 7;              // 0..7
    const uint32_t swc = (uint32_t)((c7 ^ (r8 & 7)) << 4);
    const __nv_bfloat16* gA = A + (long)(m0 + r8) * KTOT + c7 * 8;
    const __nv_bfloat16* gB = B + (long)(n0 + r8) * KTOT + c7 * 8;
    const uint32_t dA = sb + (uint32_t)(r8 * 128) + swc;
    const uint32_t dB = dA + 128 * 128;

#define LOAD_STAGE(slot, kt) do { \
        const uint32_t _o = (uint32_t)(slot) * STGB; \
        const long _k = (long)(kt) * 64; \
        _Pragma("unroll") \
        for (int _i = 0; _i < 4; _i++) \
            CP_ASYNC_16(dA + _o + _i * 32 * 128, gA + _k + (long)_i * 32 * KTOT); \
        _Pragma("unroll") \
        for (int _i = 0; _i < 8; _i++) \
            CP_ASYNC_16(dB + _o + _i * 32 * 128, gB + _k + (long)_i * 32 * KTOT); \
    } while (0)

    LOAD_STAGE(0, 0); CP_COMMIT();
    LOAD_STAGE(1, 1); CP_COMMIT();

    float acc[4][8][4];
#pragma unroll
    for (int i = 0; i < 4; i++)
#pragma unroll
        for (int j = 0; j < 8; j++)
#pragma unroll
            for (int k = 0; k < 4; k++) acc[i][j][k] = 0.f;

    // ldmatrix per-lane row offsets
    const uint32_t aRowB = (uint32_t)((wm * 64 + (lane & 15)) * 128);
    const uint32_t bRowB = (uint32_t)((wn * 64 + ((lane >> 4) << 3) + (lane & 7)) * 128);
    const uint32_t l7 = (uint32_t)(lane & 7);
    const uint32_t aC = (uint32_t)(lane >> 4);        // col16 half for A
    const uint32_t bC = (uint32_t)((lane >> 3) & 1);  // col16 half for B

    // double-buffered fragments
    uint32_t af[2][4][4], bf[2][4][4];

#define LDFRAGS(buf, Ab, Bb, kk) do { \
        const uint32_t _aSw = (((uint32_t)((kk) * 2) + aC) ^ l7) << 4; \
        const uint32_t _bSw = (((uint32_t)((kk) * 2) + bC) ^ l7) << 4; \
        _Pragma("unroll") \
        for (int _f = 0; _f < 4; _f++) \
            ldsm_x4(af[buf][_f], (Ab) + aRowB + _f * 16 * 128 + _aSw); \
        _Pragma("unroll") \
        for (int _f = 0; _f < 4; _f++) \
            ldsm_x4(bf[buf][_f], (Bb) + bRowB + _f * 16 * 128 + _bSw); \
    } while (0)

    const int NKT = KTOT / 64;   // 24
    for (int kt = 0; kt < NKT; kt++) {
        CP_WAIT1();
        __syncthreads();
        const int ktn = kt + 2;
        if (ktn < NKT) LOAD_STAGE(ktn % 3, ktn);
        CP_COMMIT();

        const uint32_t Ab = sb + (uint32_t)(kt % 3) * STGB;
        const uint32_t Bb = Ab + 128 * 128;

        LDFRAGS(0, Ab, Bb, 0);
#pragma unroll
        for (int kk = 0; kk < 4; kk++) {
            const int cur = kk & 1;
            if (kk < 3) LDFRAGS(cur ^ 1, Ab, Bb, kk + 1);
#pragma unroll
            for (int fm = 0; fm < 4; fm++)
#pragma unroll
                for (int nb = 0; nb < 8; nb++)
                    mma_16816(acc[fm][nb], af[cur][fm],
                              &bf[cur][nb >> 1][(nb & 1) * 2]);
        }
    }
#undef LDFRAGS
#undef LOAD_STAGE

    // ---- epilogue ----
    const int g = lane >> 2, t = lane & 3;
#pragma unroll
    for (int fm = 0; fm < 4; fm++) {
        const int m = m0 + wm * 64 + fm * 16 + g;
        long row0, row1;
        if (MODE == 1) {
            row0 = (long)((m & 31) * SEQ + (m >> 5)) * N;
            row1 = (long)(((m + 8) & 31) * SEQ + ((m + 8) >> 5)) * N;
        } else {
            row0 = (long)m * N;
            row1 = (long)(m + 8) * N;
        }
#pragma unroll
        for (int nb = 0; nb < 8; nb++) {
            const int n = n0 + wn * 64 + nb * 8 + t * 2;
            float2 v0, v1;
            v0.x = acc[fm][nb][0]; v0.y = acc[fm][nb][1];
            v1.x = acc[fm][nb][2]; v1.y = acc[fm][nb][3];
            if (MODE == 0) {
                const float b0 = bias[n], b1 = bias[n + 1];
                v0.x += b0; v0.y += b1;
                v1.x += b0; v1.y += b1;
            }
            *(float2*)(C + row0 + n) = v0;
            *(float2*)(C + row1 + n) = v1;
        }
    }
}

// ---------------- persistent GRU recurrence kernel -------------------------
// 64 CTAs x 768 threads (24 warps). Each CTA owns 8 hidden units.
// Warp w (0..23): gate = w>>3 (r/z/n), unit jj = w&7; w_hh row in registers.
__global__ __launch_bounds__(768) void gru_kernel(
    const float* __restrict__ hidden0,
    const float* __restrict__ w_hh,
    const float* __restrict__ b_hh)
{
    extern __shared__ float sm[];
    float* h_s  = sm;                      // [32][512]
    float* hg_s = sm + BATCH * HDIM;       // [24][32]

    const int tid  = threadIdx.x;
    const int lane = tid & 31;
    const int w    = tid >> 5;             // 0..23
    const int u0   = blockIdx.x * 8;
    const int gate = w >> 3;               // 0=r 1=z 2=n
    const int jj   = w & 7;
    const int row  = gate * HDIM + u0 + jj;

    float wreg[16];
#pragma unroll
    for (int t = 0; t < 4; t++) {
        float4 wv = *(const float4*)(w_hh + (long)row * HDIM + 4 * lane + 128 * t);
        wreg[4 * t + 0] = wv.x; wreg[4 * t + 1] = wv.y;
        wreg[4 * t + 2] = wv.z; wreg[4 * t + 3] = wv.w;
    }
    const float bias = b_hh[row];
    const int nblocks = (int)gridDim.x;

    for (int s = 0; s < SEQ; s++) {
        for (int idx = tid; idx < (BATCH * HDIM) / 4; idx += 768) {
            float4 v;
            if (s == 0) v = ((const float4*)hidden0)[idx];
            else        v = __ldcg(((const float4*)g_h) + idx);
            *(float4*)&h_s[idx * 4] = v;
        }
        __syncthreads();

#pragma unroll 4
        for (int b = 0; b < BATCH; b++) {
            const float4* hp = (const float4*)&h_s[b * HDIM + 4 * lane];
            float s0 = 0.f, s1 = 0.f;
            {
                float4 h0 = hp[0],  h1 = hp[32], h2 = hp[64], h3 = hp[96];
                s0 += wreg[0] * h0.x + wreg[1] * h0.y + wreg[2] * h0.z + wreg[3] * h0.w;
                s1 += wreg[4] * h1.x + wreg[5] * h1.y + wreg[6] * h1.z + wreg[7] * h1.w;
                s0 += wreg[8] * h2.x + wreg[9] * h2.y + wreg[10] * h2.z + wreg[11] * h2.w;
                s1 += wreg[12] * h3.x + wreg[13] * h3.y + wreg[14] * h3.z + wreg[15] * h3.w;
            }
            float sum = s0 + s1;
#pragma unroll
            for (int off = 16; off; off >>= 1)
                sum += __shfl_xor_sync(0xffffffffu, sum, off);
            if (lane == 0) hg_s[w * BATCH + b] = sum + bias;
        }
        __syncthreads();

        if (tid < 256) {
            const int b = tid & 31;
            const int j = tid >> 5;        // 0..7
            const int u = u0 + j;
            const float* xg = g_xg + ((long)s * BATCH + b) * G3H;
            const float xr = xg[u], xz = xg[HDIM + u], xn = xg[2 * HDIM + u];
            const float hr = hg_s[(0 + j) * BATCH + b];
            const float hz = hg_s[(8 + j) * BATCH + b];
            const float hn = hg_s[(16 + j) * BATCH + b];
            const float r = 1.f / (1.f + expf(-(xr + hr)));
            const float z = 1.f / (1.f + expf(-(xz + hz)));
            const float n = tanhf(xn + r * hn);
            const float ho = h_s[b * HDIM + u];
            const float hnew = (1.f - z) * n + z * ho;
            __stcg(&g_h[b * HDIM + u], hnew);
            g_hs[((long)s * BATCH + b) * HDIM + u] = hnew;
        }

        __threadfence();
        __syncthreads();
        if (tid == 0) {
            atomicAdd(&g_arrive, 1);
            const int target = nblocks * (s + 1);
            while (*((volatile int*)&g_arrive) < target) { }
            __threadfence();
        }
        __syncthreads();
    }

    if (tid == 0) {
        const int v = atomicAdd(&g_exit, 1);
        if (v == nblocks - 1) {
            g_arrive = 0;
            g_exit = 0;
            __threadfence();
        }
    }
}

// ---------------- launcher --------------------------------------------------
extern "C" void kernel_launch(void* const* d_in, const int* in_sizes, int n_in,
                              void* d_out, int out_size)
{
    const float* embed_x = (const float*)d_in[0];
    const float* hidden  = (const float*)d_in[1];
    const float* w_ih    = (const float*)d_in[2];
    const float* w_hh    = (const float*)d_in[3];
    const float* b_ih    = (const float*)d_in[4];
    const float* b_hh    = (const float*)d_in[5];
    const float* w_out   = (const float*)d_in[6];
    float* out = (float*)d_out;

    void *xg_p = nullptr, *hs_p = nullptr;
    void *axg_p = nullptr, *bxg_p = nullptr, *a_p = nullptr, *b_p = nullptr;
    cudaGetSymbolAddress(&xg_p, g_xg);
    cudaGetSymbolAddress(&hs_p, g_hs);
    cudaGetSymbolAddress(&axg_p, g_axg);
    cudaGetSymbolAddress(&bxg_p, g_bxg);
    cudaGetSymbolAddress(&a_p, g_a);
    cudaGetSymbolAddress(&b_p, g_b);

    const int smem_gru = (BATCH * HDIM + 24 * BATCH) * (int)sizeof(float); // 68608
    cudaFuncSetAttribute(gru_kernel, cudaFuncAttributeMaxDynamicSharedMemorySize,
                         smem_gru);
    cudaFuncSetAttribute(mma_gemm_kernel<0>,
                         cudaFuncAttributeMaxDynamicSharedMemorySize, SMEM_MMA);
    cudaFuncSetAttribute(mma_gemm_kernel<1>,
                         cudaFuncAttributeMaxDynamicSharedMemorySize, SMEM_MMA);

    const int M = SEQ * BATCH;   // 4096

    // 0) expand w_out -> B'
    split_expand_kernel<0, 1><<<(VDIM * 128) / 256, 256>>>(w_out,
        (__nv_bfloat16*)b_p, VDIM);

    // 1) expand embed_x -> A'_xg ; w_ih -> B'_xg
    split_expand_kernel<1, 0><<<(M * 128) / 256, 256>>>(embed_x,
        (__nv_bfloat16*)axg_p, M);
    split_expand_kernel<0, 1><<<(G3H * 128) / 256, 256>>>(w_ih,
        (__nv_bfloat16*)bxg_p, G3H);

    // 2) x_gates = embed_x @ w_ih^T + b_ih
    {
        dim3 grid(M / 128, G3H / 256);   // (32, 6)
        mma_gemm_kernel<0><<<grid, 256, SMEM_MMA>>>(
            (const __nv_bfloat16*)axg_p, (const __nv_bfloat16*)bxg_p,
            b_ih, (float*)xg_p, G3H);
    }

    // 3) GRU recurrence -> g_hs
    gru_kernel<<<64, 768, smem_gru>>>(hidden, w_hh, b_hh);

    // 4) expand hs -> A'
    split_expand_kernel<0, 0><<<(M * 128) / 256, 256>>>(
        (const float*)hs_p, (__nv_bfloat16*)a_p, M);

    // 5) logits = hs @ w_out^T -> out [b][s][v]
    {
        dim3 grid(M / 128, VDIM / 256);  // (32, 125)
        mma_gemm_kernel<1><<<grid, 256, SMEM_MMA>>>(
            (const __nv_bfloat16*)a_p, (const __nv_bfloat16*)b_p,
            nullptr, out, VDIM);
    }
}

// round 12
// speedup vs baseline: 1.4242x; 1.4242x over previous
#include <cuda_runtime.h>
#include <cuda_bf16.h>
#include <cuda_fp16.h>
#include <math.h>
#include <stdint.h>

// Problem dims
#define BATCH 32
#define SEQ   128
#define EDIM  512
#define HDIM  512
#define VDIM  32000
#define G3H   1536   // 3*HDIM
#define K3    1536   // split-3 expanded K (bf16, x_gates)
#define K2    1024   // split-2 expanded K (fp16, logits)

// ---------------- scratch (device globals: allocation-free) ----------------
__device__ __align__(256) float g_xg[SEQ * BATCH * G3H];   // [s][b][3H]
__device__ __align__(256) float g_hs[SEQ * BATCH * HDIM];  // [s][b][H]
__device__ __align__(256) float g_h [BATCH * HDIM];
__device__ int g_arrive;
__device__ int g_exit;

// bf16 split-3 operands for x_gates  (A' = [hi|hi|lo], B' = [hi|lo|hi])
__device__ __align__(256) __nv_bfloat16 g_axg[SEQ * BATCH * K3];
__device__ __align__(256) __nv_bfloat16 g_bxg[G3H * K3];
// fp16 split-2 operands for logits   (A' = [hi|lo],  B' = [hi|hi])
__device__ __align__(256) __half g_a16[SEQ * BATCH * K2];
__device__ __align__(256) __half g_b16[VDIM * K2];

// ===================== PTX helpers (plain sm_80+ PTX) =======================
__device__ __forceinline__ uint32_t smem_u32(const void* p) {
    uint32_t a;
    asm("{ .reg .u64 t; cvta.to.shared.u64 t, %1; cvt.u32.u64 %0, t; }"
        : "=r"(a) : "l"(p));
    return a;
}
#define CP_ASYNC_16(dst, src) \
    asm volatile("cp.async.cg.shared.global [%0], [%1], 16;" \
                 :: "r"(dst), "l"(src) : "memory")
#define CP_COMMIT() asm volatile("cp.async.commit_group;" ::: "memory")
#define CP_WAIT1()  asm volatile("cp.async.wait_group 1;" ::: "memory")

__device__ __forceinline__ void ldsm_x4(uint32_t* r, uint32_t addr) {
    asm volatile("ldmatrix.sync.aligned.m8n8.x4.shared.b16 {%0,%1,%2,%3}, [%4];"
                 : "=r"(r[0]), "=r"(r[1]), "=r"(r[2]), "=r"(r[3]) : "r"(addr));
}
template <int FP16>
__device__ __forceinline__ void mma_16816(float* c, const uint32_t* a,
                                          const uint32_t* b) {
    if (FP16)
        asm volatile(
            "mma.sync.aligned.m16n8k16.row.col.f32.f16.f16.f32 "
            "{%0,%1,%2,%3}, {%4,%5,%6,%7}, {%8,%9}, {%0,%1,%2,%3};"
            : "+f"(c[0]), "+f"(c[1]), "+f"(c[2]), "+f"(c[3])
            : "r"(a[0]), "r"(a[1]), "r"(a[2]), "r"(a[3]), "r"(b[0]), "r"(b[1]));
    else
        asm volatile(
            "mma.sync.aligned.m16n8k16.row.col.f32.bf16.bf16.f32 "
            "{%0,%1,%2,%3}, {%4,%5,%6,%7}, {%8,%9}, {%0,%1,%2,%3};"
            : "+f"(c[0]), "+f"(c[1]), "+f"(c[2]), "+f"(c[3])
            : "r"(a[0]), "r"(a[1]), "r"(a[2]), "r"(a[3]), "r"(b[0]), "r"(b[1]));
}

// ---------------- split/expand kernels --------------------------------------
// bf16 split-3: src fp32 [rows][512] -> dst bf16 [rows][1536]
// ISB=0 (A): [hi, hi, lo];  ISB=1 (B): [hi, lo, hi]
// REMAP=1: src row = (r&31)*SEQ + (r>>5)
template <int REMAP, int ISB>
__global__ __launch_bounds__(256) void split3_bf16_kernel(
    const float* __restrict__ src, __nv_bfloat16* __restrict__ dst, int rows)
{
    const int i = blockIdx.x * blockDim.x + threadIdx.x;
    if (i >= rows * 128) return;
    const int r = i >> 7;
    const int c4 = (i & 127) * 4;
    long srow;
    if (REMAP) srow = (long)((r & 31) * SEQ + (r >> 5)) * 512;
    else       srow = (long)r * 512;
    float4 v = *(const float4*)(src + srow + c4);
    __nv_bfloat16 h0 = __float2bfloat16(v.x), h1 = __float2bfloat16(v.y);
    __nv_bfloat16 h2 = __float2bfloat16(v.z), h3 = __float2bfloat16(v.w);
    __nv_bfloat16 l0 = __float2bfloat16(v.x - __bfloat162float(h0));
    __nv_bfloat16 l1 = __float2bfloat16(v.y - __bfloat162float(h1));
    __nv_bfloat16 l2 = __float2bfloat16(v.z - __bfloat162float(h2));
    __nv_bfloat16 l3 = __float2bfloat16(v.w - __bfloat162float(h3));
    __nv_bfloat162 hA(h0, h1), hB(h2, h3);
    __nv_bfloat162 lA(l0, l1), lB(l2, l3);
    __nv_bfloat16* d = dst + (long)r * K3 + c4;
    *(__nv_bfloat162*)(d + 0) = hA; *(__nv_bfloat162*)(d + 2) = hB;
    if (ISB) {
        *(__nv_bfloat162*)(d + 512)  = lA; *(__nv_bfloat162*)(d + 514)  = lB;
        *(__nv_bfloat162*)(d + 1024) = hA; *(__nv_bfloat162*)(d + 1026) = hB;
    } else {
        *(__nv_bfloat162*)(d + 512)  = hA; *(__nv_bfloat162*)(d + 514)  = hB;
        *(__nv_bfloat162*)(d + 1024) = lA; *(__nv_bfloat162*)(d + 1026) = lB;
    }
}

// fp16 split-2: src fp32 [rows][512] -> dst fp16 [rows][1024]
// ISB=0 (A): [hi, lo];  ISB=1 (B): [hi, hi]
template <int ISB>
__global__ __launch_bounds__(256) void split2_fp16_kernel(
    const float* __restrict__ src, __half* __restrict__ dst, int rows)
{
    const int i = blockIdx.x * blockDim.x + threadIdx.x;
    if (i >= rows * 128) return;
    const int r = i >> 7;
    const int c4 = (i & 127) * 4;
    float4 v = *(const float4*)(src + (long)r * 512 + c4);
    __half h0 = __float2half(v.x), h1 = __float2half(v.y);
    __half h2 = __float2half(v.z), h3 = __float2half(v.w);
    __half2 hA(h0, h1), hB(h2, h3);
    __half* d = dst + (long)r * K2 + c4;
    *(__half2*)(d + 0) = hA; *(__half2*)(d + 2) = hB;
    if (ISB) {
        *(__half2*)(d + 512) = hA; *(__half2*)(d + 514) = hB;
    } else {
        __half l0 = __float2half(v.x - __half2float(h0));
        __half l1 = __float2half(v.y - __half2float(h1));
        __half l2 = __float2half(v.z - __half2float(h2));
        __half l3 = __float2half(v.w - __half2float(h3));
        *(__half2*)(d + 512) = __half2(l0, l1);
        *(__half2*)(d + 514) = __half2(l2, l3);
    }
}

// ---------------- HMMA GEMM: C[M,N] = A'[M,KK] * B'[N,KK]^T -----------------
// CTA tile 128(M) x 256(N), 8 warps (2m x 4n), warp tile 64x64.
// K-step 64 (128B rows, XOR swizzle), 3-stage cp.async, 256 threads.
// MODE 0: +bias, C row = m.   MODE 1: no bias, C row = (m&31)*SEQ+(m>>5).
#define STGB ((128 + 256) * 128)       // 49152 per stage: A(128 rows) then B(256)
#define NSTG 3
#define SMEM_MMA (NSTG * STGB)         // 147456

template <int MODE, int KK, int FP16, typename T>
__global__ __launch_bounds__(256, 1) void mma_gemm_kernel(
    const T* __restrict__ A, const T* __restrict__ B,
    const float* __restrict__ bias, float* __restrict__ C, int N)
{
    extern __shared__ char smem[];
    const uint32_t sb = smem_u32(smem);
    const int tid  = threadIdx.x;
    const int wid  = tid >> 5, lane = tid & 31;
    const int m0   = blockIdx.x * 128;
    const int n0   = blockIdx.y * 256;
    const int wm   = wid & 1;            // 2 warps along m (64 each)
    const int wn   = wid >> 1;           // 4 warps along n (64 each)

    // ---- cp.async mapping: row = r8 (+32*i), col16 = c7
    const int r8 = tid >> 3;             // 0..31
    const int c7 = tid & 7;              // 0..7
    const uint32_t swc = (uint32_t)((c7 ^ (r8 & 7)) << 4);
    const T* gA = A + (long)(m0 + r8) * KK + c7 * 8;
    const T* gB = B + (long)(n0 + r8) * KK + c7 * 8;
    const uint32_t dA = sb + (uint32_t)(r8 * 128) + swc;
    const uint32_t dB = dA + 128 * 128;

#define LOAD_STAGE(slot, kt) do { \
        const uint32_t _o = (uint32_t)(slot) * STGB; \
        const long _k = (long)(kt) * 64; \
        _Pragma("unroll") \
        for (int _i = 0; _i < 4; _i++) \
            CP_ASYNC_16(dA + _o + _i * 32 * 128, gA + _k + (long)_i * 32 * KK); \
        _Pragma("unroll") \
        for (int _i = 0; _i < 8; _i++) \
            CP_ASYNC_16(dB + _o + _i * 32 * 128, gB + _k + (long)_i * 32 * KK); \
    } while (0)

    LOAD_STAGE(0, 0); CP_COMMIT();
    LOAD_STAGE(1, 1); CP_COMMIT();

    float acc[4][8][4];
#pragma unroll
    for (int i = 0; i < 4; i++)
#pragma unroll
        for (int j = 0; j < 8; j++)
#pragma unroll
            for (int k = 0; k < 4; k++) acc[i][j][k] = 0.f;

    // ldmatrix per-lane row offsets
    const uint32_t aRowB = (uint32_t)((wm * 64 + (lane & 15)) * 128);
    const uint32_t bRowB = (uint32_t)((wn * 64 + ((lane >> 4) << 3) + (lane & 7)) * 128);
    const uint32_t l7 = (uint32_t)(lane & 7);
    const uint32_t aC = (uint32_t)(lane >> 4);        // col16 half for A
    const uint32_t bC = (uint32_t)((lane >> 3) & 1);  // col16 half for B

    const int NKT = KK / 64;
    for (int kt = 0; kt < NKT; kt++) {
        CP_WAIT1();
        __syncthreads();
        const int ktn = kt + 2;
        if (ktn < NKT) LOAD_STAGE(ktn % 3, ktn);
        CP_COMMIT();

        const uint32_t Ab = sb + (uint32_t)(kt % 3) * STGB;
        const uint32_t Bb = Ab + 128 * 128;
#pragma unroll
        for (int kk = 0; kk < 4; kk++) {
            const uint32_t aSw = (((uint32_t)(kk * 2) + aC) ^ l7) << 4;
            const uint32_t bSw = (((uint32_t)(kk * 2) + bC) ^ l7) << 4;
            uint32_t af[4][4];
#pragma unroll
            for (int fm = 0; fm < 4; fm++)
                ldsm_x4(af[fm], Ab + aRowB + fm * 16 * 128 + aSw);
            uint32_t bf[4][4];
#pragma unroll
            for (int nb2 = 0; nb2 < 4; nb2++)
                ldsm_x4(bf[nb2], Bb + bRowB + nb2 * 16 * 128 + bSw);
#pragma unroll
            for (int fm = 0; fm < 4; fm++)
#pragma unroll
                for (int nb = 0; nb < 8; nb++)
                    mma_16816<FP16>(acc[fm][nb], af[fm],
                                    &bf[nb >> 1][(nb & 1) * 2]);
        }
    }
#undef LOAD_STAGE

    // ---- epilogue ----
    const int g = lane >> 2, t = lane & 3;
#pragma unroll
    for (int fm = 0; fm < 4; fm++) {
        const int m = m0 + wm * 64 + fm * 16 + g;
        long row0, row1;
        if (MODE == 1) {
            row0 = (long)((m & 31) * SEQ + (m >> 5)) * N;
            row1 = (long)(((m + 8) & 31) * SEQ + ((m + 8) >> 5)) * N;
        } else {
            row0 = (long)m * N;
            row1 = (long)(m + 8) * N;
        }
#pragma unroll
        for (int nb = 0; nb < 8; nb++) {
            const int n = n0 + wn * 64 + nb * 8 + t * 2;
            float2 v0, v1;
            v0.x = acc[fm][nb][0]; v0.y = acc[fm][nb][1];
            v1.x = acc[fm][nb][2]; v1.y = acc[fm][nb][3];
            if (MODE == 0) {
                const float b0 = bias[n], b1 = bias[n + 1];
                v0.x += b0; v0.y += b1;
                v1.x += b0; v1.y += b1;
            }
            *(float2*)(C + row0 + n) = v0;
            *(float2*)(C + row1 + n) = v1;
        }
    }
}

// ---------------- persistent GRU recurrence kernel (R7 proven) -------------
__global__ __launch_bounds__(384) void gru_kernel(
    const float* __restrict__ hidden0,
    const float* __restrict__ w_hh,
    const float* __restrict__ b_hh)
{
    extern __shared__ float sm[];
    float* h_s  = sm;
    float* hg_s = sm + BATCH * HDIM;

    const int tid  = threadIdx.x;
    const int lane = tid & 31;
    const int w    = tid >> 5;
    const int u0   = blockIdx.x * 4;
    const int gate = w >> 2;
    const int jj   = w & 3;
    const int row  = gate * HDIM + u0 + jj;

    float wreg[16];
#pragma unroll
    for (int t = 0; t < 4; t++) {
        float4 wv = *(const float4*)(w_hh + (long)row * HDIM + 4 * lane + 128 * t);
        wreg[4 * t + 0] = wv.x; wreg[4 * t + 1] = wv.y;
        wreg[4 * t + 2] = wv.z; wreg[4 * t + 3] = wv.w;
    }
    const float bias = b_hh[row];
    const int nblocks = (int)gridDim.x;

    for (int s = 0; s < SEQ; s++) {
        for (int idx = tid; idx < (BATCH * HDIM) / 4; idx += 384) {
            float4 v;
            if (s == 0) v = ((const float4*)hidden0)[idx];
            else        v = __ldcg(((const float4*)g_h) + idx);
            *(float4*)&h_s[idx * 4] = v;
        }
        __syncthreads();

#pragma unroll 4
        for (int b = 0; b < BATCH; b++) {
            const float4* hp = (const float4*)&h_s[b * HDIM + 4 * lane];
            float s0 = 0.f, s1 = 0.f;
            {
                float4 h0 = hp[0],  h1 = hp[32], h2 = hp[64], h3 = hp[96];
                s0 += wreg[0] * h0.x + wreg[1] * h0.y + wreg[2] * h0.z + wreg[3] * h0.w;
                s1 += wreg[4] * h1.x + wreg[5] * h1.y + wreg[6] * h1.z + wreg[7] * h1.w;
                s0 += wreg[8] * h2.x + wreg[9] * h2.y + wreg[10] * h2.z + wreg[11] * h2.w;
                s1 += wreg[12] * h3.x + wreg[13] * h3.y + wreg[14] * h3.z + wreg[15] * h3.w;
            }
            float sum = s0 + s1;
#pragma unroll
            for (int off = 16; off; off >>= 1)
                sum += __shfl_xor_sync(0xffffffffu, sum, off);
            if (lane == 0) hg_s[w * BATCH + b] = sum + bias;
        }
        __syncthreads();

        if (tid < 128) {
            const int b = tid & 31;
            const int j = tid >> 5;
            const int u = u0 + j;
            const float* xg = g_xg + ((long)s * BATCH + b) * G3H;
            const float xr = xg[u], xz = xg[HDIM + u], xn = xg[2 * HDIM + u];
            const float hr = hg_s[(0 + j) * BATCH + b];
            const float hz = hg_s[(4 + j) * BATCH + b];
            const float hn = hg_s[(8 + j) * BATCH + b];
            const float r = 1.f / (1.f + expf(-(xr + hr)));
            const float z = 1.f / (1.f + expf(-(xz + hz)));
            const float n = tanhf(xn + r * hn);
            const float ho = h_s[b * HDIM + u];
            const float hnew = (1.f - z) * n + z * ho;
            __stcg(&g_h[b * HDIM + u], hnew);
            g_hs[((long)s * BATCH + b) * HDIM + u] = hnew;
        }

        __threadfence();
        __syncthreads();
        if (tid == 0) {
            atomicAdd(&g_arrive, 1);
            const int target = nblocks * (s + 1);
            while (*((volatile int*)&g_arrive) < target) { }
            __threadfence();
        }
        __syncthreads();
    }

    if (tid == 0) {
        const int v = atomicAdd(&g_exit, 1);
        if (v == nblocks - 1) {
            g_arrive = 0;
            g_exit = 0;
            __threadfence();
        }
    }
}

// ---------------- launcher --------------------------------------------------
extern "C" void kernel_launch(void* const* d_in, const int* in_sizes, int n_in,
                              void* d_out, int out_size)
{
    const float* embed_x = (const float*)d_in[0];
    const float* hidden  = (const float*)d_in[1];
    const float* w_ih    = (const float*)d_in[2];
    const float* w_hh    = (const float*)d_in[3];
    const float* b_ih    = (const float*)d_in[4];
    const float* b_hh    = (const float*)d_in[5];
    const float* w_out   = (const float*)d_in[6];
    float* out = (float*)d_out;

    void *xg_p = nullptr, *hs_p = nullptr;
    void *axg_p = nullptr, *bxg_p = nullptr, *a16_p = nullptr, *b16_p = nullptr;
    cudaGetSymbolAddress(&xg_p, g_xg);
    cudaGetSymbolAddress(&hs_p, g_hs);
    cudaGetSymbolAddress(&axg_p, g_axg);
    cudaGetSymbolAddress(&bxg_p, g_bxg);
    cudaGetSymbolAddress(&a16_p, g_a16);
    cudaGetSymbolAddress(&b16_p, g_b16);

    const int smem_gru = (BATCH * HDIM + 12 * BATCH) * (int)sizeof(float);
    cudaFuncSetAttribute(gru_kernel, cudaFuncAttributeMaxDynamicSharedMemorySize,
                         smem_gru);
    cudaFuncSetAttribute(mma_gemm_kernel<0, K3, 0, __nv_bfloat16>,
                         cudaFuncAttributeMaxDynamicSharedMemorySize, SMEM_MMA);
    cudaFuncSetAttribute(mma_gemm_kernel<1, K2, 1, __half>,
                         cudaFuncAttributeMaxDynamicSharedMemorySize, SMEM_MMA);

    const int M = SEQ * BATCH;   // 4096

    // 0) expand w_out -> fp16 B' [hi|hi]
    split2_fp16_kernel<1><<<(VDIM * 128) / 256, 256>>>(w_out,
        (__half*)b16_p, VDIM);

    // 1) expand embed_x -> bf16 A'_xg ; w_ih -> bf16 B'_xg
    split3_bf16_kernel<1, 0><<<(M * 128) / 256, 256>>>(embed_x,
        (__nv_bfloat16*)axg_p, M);
    split3_bf16_kernel<0, 1><<<(G3H * 128) / 256, 256>>>(w_ih,
        (__nv_bfloat16*)bxg_p, G3H);

    // 2) x_gates = embed_x @ w_ih^T + b_ih  (bf16 split-3)
    {
        dim3 grid(M / 128, G3H / 256);   // (32, 6)
        mma_gemm_kernel<0, K3, 0, __nv_bfloat16><<<grid, 256, SMEM_MMA>>>(
            (const __nv_bfloat16*)axg_p, (const __nv_bfloat16*)bxg_p,
            b_ih, (float*)xg_p, G3H);
    }

    // 3) GRU recurrence -> g_hs
    gru_kernel<<<128, 384, smem_gru>>>(hidden, w_hh, b_hh);

    // 4) expand hs -> fp16 A' [hi|lo]
    split2_fp16_kernel<0><<<(M * 128) / 256, 256>>>(
        (const float*)hs_p, (__half*)a16_p, M);

    // 5) logits = hs @ w_out^T -> out [b][s][v]  (fp16 split-2)
    {
        dim3 grid(M / 128, VDIM / 256);  // (32, 125)
        mma_gemm_kernel<1, K2, 1, __half><<<grid, 256, SMEM_MMA>>>(
            (const __half*)a16_p, (const __half*)b16_p,
            nullptr, out, VDIM);
    }
}

// round 14
// speedup vs baseline: 1.6813x; 1.1806x over previous
#include <cuda_runtime.h>
#include <cuda_bf16.h>
#include <cuda_fp16.h>
#include <math.h>
#include <stdint.h>

// Problem dims
#define BATCH 32
#define SEQ   128
#define EDIM  512
#define HDIM  512
#define VDIM  32000
#define G3H   1536   // 3*HDIM
#define K3    1536   // split-3 expanded K (bf16, x_gates)

// ---------------- scratch (device globals: allocation-free) ----------------
__device__ __align__(256) float g_xg[SEQ * BATCH * G3H];   // [s][b][3H]
__device__ __align__(256) float g_h [BATCH * HDIM];
__device__ int g_arrive;
__device__ int g_exit;

// bf16 split-3 operands for x_gates  (A' = [hi|hi|lo], B' = [hi|lo|hi])
__device__ __align__(256) __nv_bfloat16 g_axg[SEQ * BATCH * K3];
__device__ __align__(256) __nv_bfloat16 g_bxg[G3H * K3];
// fp16 operands for logits (plain hi-only, K = 512)
__device__ __align__(256) __half g_hs16[SEQ * BATCH * HDIM];  // written by GRU
__device__ __align__(256) __half g_b16 [VDIM * HDIM];         // w_out fp16

// ===================== PTX helpers (plain sm_80+ PTX) =======================
__device__ __forceinline__ uint32_t smem_u32(const void* p) {
    uint32_t a;
    asm("{ .reg .u64 t; cvta.to.shared.u64 t, %1; cvt.u32.u64 %0, t; }"
        : "=r"(a) : "l"(p));
    return a;
}
#define CP_ASYNC_16(dst, src) \
    asm volatile("cp.async.cg.shared.global [%0], [%1], 16;" \
                 :: "r"(dst), "l"(src) : "memory")
#define CP_COMMIT() asm volatile("cp.async.commit_group;" ::: "memory")
#define CP_WAIT1()  asm volatile("cp.async.wait_group 1;" ::: "memory")

__device__ __forceinline__ void ldsm_x4(uint32_t* r, uint32_t addr) {
    asm volatile("ldmatrix.sync.aligned.m8n8.x4.shared.b16 {%0,%1,%2,%3}, [%4];"
                 : "=r"(r[0]), "=r"(r[1]), "=r"(r[2]), "=r"(r[3]) : "r"(addr));
}
template <int FP16>
__device__ __forceinline__ void mma_16816(float* c, const uint32_t* a,
                                          const uint32_t* b) {
    if (FP16)
        asm volatile(
            "mma.sync.aligned.m16n8k16.row.col.f32.f16.f16.f32 "
            "{%0,%1,%2,%3}, {%4,%5,%6,%7}, {%8,%9}, {%0,%1,%2,%3};"
            : "+f"(c[0]), "+f"(c[1]), "+f"(c[2]), "+f"(c[3])
            : "r"(a[0]), "r"(a[1]), "r"(a[2]), "r"(a[3]), "r"(b[0]), "r"(b[1]));
    else
        asm volatile(
            "mma.sync.aligned.m16n8k16.row.col.f32.bf16.bf16.f32 "
            "{%0,%1,%2,%3}, {%4,%5,%6,%7}, {%8,%9}, {%0,%1,%2,%3};"
            : "+f"(c[0]), "+f"(c[1]), "+f"(c[2]), "+f"(c[3])
            : "r"(a[0]), "r"(a[1]), "r"(a[2]), "r"(a[3]), "r"(b[0]), "r"(b[1]));
}

// ---------------- split/convert kernels -------------------------------------
// bf16 split-3: src fp32 [rows][512] -> dst bf16 [rows][1536]
// ISB=0 (A): [hi, hi, lo];  ISB=1 (B): [hi, lo, hi]
// REMAP=1: src row = (r&31)*SEQ + (r>>5)
template <int REMAP, int ISB>
__global__ __launch_bounds__(256) void split3_bf16_kernel(
    const float* __restrict__ src, __nv_bfloat16* __restrict__ dst, int rows)
{
    const int i = blockIdx.x * blockDim.x + threadIdx.x;
    if (i >= rows * 128) return;
    const int r = i >> 7;
    const int c4 = (i & 127) * 4;
    long srow;
    if (REMAP) srow = (long)((r & 31) * SEQ + (r >> 5)) * 512;
    else       srow = (long)r * 512;
    float4 v = *(const float4*)(src + srow + c4);
    __nv_bfloat16 h0 = __float2bfloat16(v.x), h1 = __float2bfloat16(v.y);
    __nv_bfloat16 h2 = __float2bfloat16(v.z), h3 = __float2bfloat16(v.w);
    __nv_bfloat16 l0 = __float2bfloat16(v.x - __bfloat162float(h0));
    __nv_bfloat16 l1 = __float2bfloat16(v.y - __bfloat162float(h1));
    __nv_bfloat16 l2 = __float2bfloat16(v.z - __bfloat162float(h2));
    __nv_bfloat16 l3 = __float2bfloat16(v.w - __bfloat162float(h3));
    __nv_bfloat162 hA(h0, h1), hB(h2, h3);
    __nv_bfloat162 lA(l0, l1), lB(l2, l3);
    __nv_bfloat16* d = dst + (long)r * K3 + c4;
    *(__nv_bfloat162*)(d + 0) = hA; *(__nv_bfloat162*)(d + 2) = hB;
    if (ISB) {
        *(__nv_bfloat162*)(d + 512)  = lA; *(__nv_bfloat162*)(d + 514)  = lB;
        *(__nv_bfloat162*)(d + 1024) = hA; *(__nv_bfloat162*)(d + 1026) = hB;
    } else {
        *(__nv_bfloat162*)(d + 512)  = hA; *(__nv_bfloat162*)(d + 514)  = hB;
        *(__nv_bfloat162*)(d + 1024) = lA; *(__nv_bfloat162*)(d + 1026) = lB;
    }
}

// plain fp32 -> fp16 convert (w_out), [rows][512]
__global__ __launch_bounds__(256) void cvt_fp16_kernel(
    const float* __restrict__ src, __half* __restrict__ dst, int rows)
{
    const int i = blockIdx.x * blockDim.x + threadIdx.x;
    if (i >= rows * 128) return;
    float4 v = ((const float4*)src)[i];
    __half2 a(__float2half(v.x), __float2half(v.y));
    __half2 b(__float2half(v.z), __float2half(v.w));
    ((__half2*)dst)[i * 2 + 0] = a;
    ((__half2*)dst)[i * 2 + 1] = b;
}

// ---------------- HMMA GEMM: C[M,N] = A'[M,KK] * B'[N,KK]^T -----------------
// CTA tile 128(M) x 256(N), 8 warps (2m x 4n), warp tile 64x64.
// K-step 64 (128B rows, XOR swizzle), 3-stage cp.async, 256 threads.
// MODE 0: +bias, C row = m.   MODE 1: no bias, C row = (m&31)*SEQ+(m>>5),
//         streaming stores (output not reused).
#define STGB ((128 + 256) * 128)       // 49152 per stage: A(128 rows) then B(256)
#define NSTG 3
#define SMEM_MMA (NSTG * STGB)         // 147456

template <int MODE, int KK, int FP16, typename T>
__global__ __launch_bounds__(256, 1) void mma_gemm_kernel(
    const T* __restrict__ A, const T* __restrict__ B,
    const float* __restrict__ bias, float* __restrict__ C, int N)
{
    extern __shared__ char smem[];
    const uint32_t sb = smem_u32(smem);
    const int tid  = threadIdx.x;
    const int wid  = tid >> 5, lane = tid & 31;
    const int m0   = blockIdx.x * 128;
    const int n0   = blockIdx.y * 256;
    const int wm   = wid & 1;            // 2 warps along m (64 each)
    const int wn   = wid >> 1;           // 4 warps along n (64 each)

    // ---- cp.async mapping: row = r8 (+32*i), col16 = c7
    const int r8 = tid >> 3;             // 0..31
    const int c7 = tid & 7;              // 0..7
    const uint32_t swc = (uint32_t)((c7 ^ (r8 & 7)) << 4);
    const T* gA = A + (long)(m0 + r8) * KK + c7 * 8;
    const T* gB = B + (long)(n0 + r8) * KK + c7 * 8;
    const uint32_t dA = sb + (uint32_t)(r8 * 128) + swc;
    const uint32_t dB = dA + 128 * 128;

#define LOAD_STAGE(slot, kt) do { \
        const uint32_t _o = (uint32_t)(slot) * STGB; \
        const long _k = (long)(kt) * 64; \
        _Pragma("unroll") \
        for (int _i = 0; _i < 4; _i++) \
            CP_ASYNC_16(dA + _o + _i * 32 * 128, gA + _k + (long)_i * 32 * KK); \
        _Pragma("unroll") \
        for (int _i = 0; _i < 8; _i++) \
            CP_ASYNC_16(dB + _o + _i * 32 * 128, gB + _k + (long)_i * 32 * KK); \
    } while (0)

    LOAD_STAGE(0, 0); CP_COMMIT();
    LOAD_STAGE(1, 1); CP_COMMIT();

    float acc[4][8][4];
#pragma unroll
    for (int i = 0; i < 4; i++)
#pragma unroll
        for (int j = 0; j < 8; j++)
#pragma unroll
            for (int k = 0; k < 4; k++) acc[i][j][k] = 0.f;

    // ldmatrix per-lane row offsets
    const uint32_t aRowB = (uint32_t)((wm * 64 + (lane & 15)) * 128);
    const uint32_t bRowB = (uint32_t)((wn * 64 + ((lane >> 4) << 3) + (lane & 7)) * 128);
    const uint32_t l7 = (uint32_t)(lane & 7);
    const uint32_t aC = (uint32_t)(lane >> 4);        // col16 half for A
    const uint32_t bC = (uint32_t)((lane >> 3) & 1);  // col16 half for B

    const int NKT = KK / 64;
    for (int kt = 0; kt < NKT; kt++) {
        CP_WAIT1();
        __syncthreads();
        const int ktn = kt + 2;
        if (ktn < NKT) LOAD_STAGE(ktn % 3, ktn);
        CP_COMMIT();

        const uint32_t Ab = sb + (uint32_t)(kt % 3) * STGB;
        const uint32_t Bb = Ab + 128 * 128;
#pragma unroll
        for (int kk = 0; kk < 4; kk++) {
            const uint32_t aSw = (((uint32_t)(kk * 2) + aC) ^ l7) << 4;
            const uint32_t bSw = (((uint32_t)(kk * 2) + bC) ^ l7) << 4;
            uint32_t af[4][4];
#pragma unroll
            for (int fm = 0; fm < 4; fm++)
                ldsm_x4(af[fm], Ab + aRowB + fm * 16 * 128 + aSw);
            uint32_t bf[4][4];
#pragma unroll
            for (int nb2 = 0; nb2 < 4; nb2++)
                ldsm_x4(bf[nb2], Bb + bRowB + nb2 * 16 * 128 + bSw);
#pragma unroll
            for (int fm = 0; fm < 4; fm++)
#pragma unroll
                for (int nb = 0; nb < 8; nb++)
                    mma_16816<FP16>(acc[fm][nb], af[fm],
                                    &bf[nb >> 1][(nb & 1) * 2]);
        }
    }
#undef LOAD_STAGE

    // ---- epilogue ----
    const int g = lane >> 2, t = lane & 3;
#pragma unroll
    for (int fm = 0; fm < 4; fm++) {
        const int m = m0 + wm * 64 + fm * 16 + g;
        long row0, row1;
        if (MODE == 1) {
            row0 = (long)((m & 31) * SEQ + (m >> 5)) * N;
            row1 = (long)(((m + 8) & 31) * SEQ + ((m + 8) >> 5)) * N;
        } else {
            row0 = (long)m * N;
            row1 = (long)(m + 8) * N;
        }
#pragma unroll
        for (int nb = 0; nb < 8; nb++) {
            const int n = n0 + wn * 64 + nb * 8 + t * 2;
            float2 v0, v1;
            v0.x = acc[fm][nb][0]; v0.y = acc[fm][nb][1];
            v1.x = acc[fm][nb][2]; v1.y = acc[fm][nb][3];
            if (MODE == 0) {
                const float b0 = bias[n], b1 = bias[n + 1];
                v0.x += b0; v0.y += b1;
                v1.x += b0; v1.y += b1;
                *(float2*)(C + row0 + n) = v0;
                *(float2*)(C + row1 + n) = v1;
            } else {
                __stcs((float2*)(C + row0 + n), v0);
                __stcs((float2*)(C + row1 + n), v1);
            }
        }
    }
}

// ---------------- persistent GRU recurrence kernel (R7 proven shape) -------
// Writes hs directly as fp16 (feeds only the logits GEMM).
__global__ __launch_bounds__(384) void gru_kernel(
    const float* __restrict__ hidden0,
    const float* __restrict__ w_hh,
    const float* __restrict__ b_hh)
{
    extern __shared__ float sm[];
    float* h_s  = sm;
    float* hg_s = sm + BATCH * HDIM;

    const int tid  = threadIdx.x;
    const int lane = tid & 31;
    const int w    = tid >> 5;
    const int u0   = blockIdx.x * 4;
    const int gate = w >> 2;
    const int jj   = w & 3;
    const int row  = gate * HDIM + u0 + jj;

    float wreg[16];
#pragma unroll
    for (int t = 0; t < 4; t++) {
        float4 wv = *(const float4*)(w_hh + (long)row * HDIM + 4 * lane + 128 * t);
        wreg[4 * t + 0] = wv.x; wreg[4 * t + 1] = wv.y;
        wreg[4 * t + 2] = wv.z; wreg[4 * t + 3] = wv.w;
    }
    const float bias = b_hh[row];
    const int nblocks = (int)gridDim.x;

    for (int s = 0; s < SEQ; s++) {
        for (int idx = tid; idx < (BATCH * HDIM) / 4; idx += 384) {
            float4 v;
            if (s == 0) v = ((const float4*)hidden0)[idx];
            else        v = __ldcg(((const float4*)g_h) + idx);
            *(float4*)&h_s[idx * 4] = v;
        }
        __syncthreads();

#pragma unroll 4
        for (int b = 0; b < BATCH; b++) {
            const float4* hp = (const float4*)&h_s[b * HDIM + 4 * lane];
            float s0 = 0.f, s1 = 0.f;
            {
                float4 h0 = hp[0],  h1 = hp[32], h2 = hp[64], h3 = hp[96];
                s0 += wreg[0] * h0.x + wreg[1] * h0.y + wreg[2] * h0.z + wreg[3] * h0.w;
                s1 += wreg[4] * h1.x + wreg[5] * h1.y + wreg[6] * h1.z + wreg[7] * h1.w;
                s0 += wreg[8] * h2.x + wreg[9] * h2.y + wreg[10] * h2.z + wreg[11] * h2.w;
                s1 += wreg[12] * h3.x + wreg[13] * h3.y + wreg[14] * h3.z + wreg[15] * h3.w;
            }
            float sum = s0 + s1;
#pragma unroll
            for (int off = 16; off; off >>= 1)
                sum += __shfl_xor_sync(0xffffffffu, sum, off);
            if (lane == 0) hg_s[w * BATCH + b] = sum + bias;
        }
        __syncthreads();

        if (tid < 128) {
            const int b = tid & 31;
            const int j = tid >> 5;
            const int u = u0 + j;
            const float* xg = g_xg + ((long)s * BATCH + b) * G3H;
            const float xr = xg[u], xz = xg[HDIM + u], xn = xg[2 * HDIM + u];
            const float hr = hg_s[(0 + j) * BATCH + b];
            const float hz = hg_s[(4 + j) * BATCH + b];
            const float hn = hg_s[(8 + j) * BATCH + b];
            const float r = 1.f / (1.f + expf(-(xr + hr)));
            const float z = 1.f / (1.f + expf(-(xz + hz)));
            const float n = tanhf(xn + r * hn);
            const float ho = h_s[b * HDIM + u];
            const float hnew = (1.f - z) * n + z * ho;
            __stcg(&g_h[b * HDIM + u], hnew);
            g_hs16[((long)s * BATCH + b) * HDIM + u] = __float2half(hnew);
        }

        __threadfence();
        __syncthreads();
        if (tid == 0) {
            atomicAdd(&g_arrive, 1);
            const int target = nblocks * (s + 1);
            while (*((volatile int*)&g_arrive) < target) { }
            __threadfence();
        }
        __syncthreads();
    }

    if (tid == 0) {
        const int v = atomicAdd(&g_exit, 1);
        if (v == nblocks - 1) {
            g_arrive = 0;
            g_exit = 0;
            __threadfence();
        }
    }
}

// ---------------- launcher --------------------------------------------------
extern "C" void kernel_launch(void* const* d_in, const int* in_sizes, int n_in,
                              void* d_out, int out_size)
{
    const float* embed_x = (const float*)d_in[0];
    const float* hidden  = (const float*)d_in[1];
    const float* w_ih    = (const float*)d_in[2];
    const float* w_hh    = (const float*)d_in[3];
    const float* b_ih    = (const float*)d_in[4];
    const float* b_hh    = (const float*)d_in[5];
    const float* w_out   = (const float*)d_in[6];
    float* out = (float*)d_out;

    void *xg_p = nullptr, *axg_p = nullptr, *bxg_p = nullptr;
    void *hs16_p = nullptr, *b16_p = nullptr;
    cudaGetSymbolAddress(&xg_p, g_xg);
    cudaGetSymbolAddress(&axg_p, g_axg);
    cudaGetSymbolAddress(&bxg_p, g_bxg);
    cudaGetSymbolAddress(&hs16_p, g_hs16);
    cudaGetSymbolAddress(&b16_p, g_b16);

    const int smem_gru = (BATCH * HDIM + 12 * BATCH) * (int)sizeof(float);
    cudaFuncSetAttribute(gru_kernel, cudaFuncAttributeMaxDynamicSharedMemorySize,
                         smem_gru);
    cudaFuncSetAttribute(mma_gemm_kernel<0, K3, 0, __nv_bfloat16>,
                         cudaFuncAttributeMaxDynamicSharedMemorySize, SMEM_MMA);
    cudaFuncSetAttribute(mma_gemm_kernel<1, HDIM, 1, __half>,
                         cudaFuncAttributeMaxDynamicSharedMemorySize, SMEM_MMA);

    const int M = SEQ * BATCH;   // 4096

    // 0) w_out -> fp16 (plain convert, K=512)
    cvt_fp16_kernel<<<(VDIM * 128) / 256, 256>>>(w_out, (__half*)b16_p, VDIM);

    // 1) expand embed_x -> bf16 A'_xg ; w_ih -> bf16 B'_xg
    split3_bf16_kernel<1, 0><<<(M * 128) / 256, 256>>>(embed_x,
        (__nv_bfloat16*)axg_p, M);
    split3_bf16_kernel<0, 1><<<(G3H * 128) / 256, 256>>>(w_ih,
        (__nv_bfloat16*)bxg_p, G3H);

    // 2) x_gates = embed_x @ w_ih^T + b_ih  (bf16 split-3)
    {
        dim3 grid(M / 128, G3H / 256);   // (32, 6)
        mma_gemm_kernel<0, K3, 0, __nv_bfloat16><<<grid, 256, SMEM_MMA>>>(
            (const __nv_bfloat16*)axg_p, (const __nv_bfloat16*)bxg_p,
            b_ih, (float*)xg_p, G3H);
    }

    // 3) GRU recurrence -> g_hs16 (fp16 A-side of logits)
    gru_kernel<<<128, 384, smem_gru>>>(hidden, w_hh, b_hh);

    // 4) logits = hs @ w_out^T -> out [b][s][v]  (plain fp16, K=512)
    {
        dim3 grid(M / 128, VDIM / 256);  // (32, 125)
        mma_gemm_kernel<1, HDIM, 1, __half><<<grid, 256, SMEM_MMA>>>(
            (const __half*)hs16_p, (const __half*)b16_p,
            nullptr, out, VDIM);
    }
}

// round 15
// speedup vs baseline: 1.6843x; 1.0017x over previous
#include <cuda_runtime.h>
#include <cuda_bf16.h>
#include <cuda_fp16.h>
#include <math.h>
#include <stdint.h>

// Problem dims
#define BATCH 32
#define SEQ   128
#define EDIM  512
#define HDIM  512
#define VDIM  32000
#define G3H   1536   // 3*HDIM
#define K3    1536   // split-3 expanded K (bf16, x_gates)

// ---------------- scratch (device globals: allocation-free) ----------------
__device__ __align__(256) float g_xg[SEQ * BATCH * G3H];   // [s][b][3H]
__device__ __align__(256) float g_h [BATCH * HDIM];
__device__ int g_arrive;
__device__ int g_exit;

// bf16 split-3 operands for x_gates  (A' = [hi|hi|lo], B' = [hi|lo|hi])
__device__ __align__(256) __nv_bfloat16 g_axg[SEQ * BATCH * K3];
__device__ __align__(256) __nv_bfloat16 g_bxg[G3H * K3];
// fp16 operands for logits (plain hi-only, K = 512)
__device__ __align__(256) __half g_hs16[SEQ * BATCH * HDIM];  // written by GRU
__device__ __align__(256) __half g_b16 [VDIM * HDIM];         // w_out fp16

// ===================== PTX helpers (plain sm_80+ PTX) =======================
__device__ __forceinline__ uint32_t smem_u32(const void* p) {
    uint32_t a;
    asm("{ .reg .u64 t; cvta.to.shared.u64 t, %1; cvt.u32.u64 %0, t; }"
        : "=r"(a) : "l"(p));
    return a;
}
#define CP_ASYNC_16(dst, src) \
    asm volatile("cp.async.cg.shared.global [%0], [%1], 16;" \
                 :: "r"(dst), "l"(src) : "memory")
#define CP_COMMIT() asm volatile("cp.async.commit_group;" ::: "memory")
#define CP_WAIT1()  asm volatile("cp.async.wait_group 1;" ::: "memory")

__device__ __forceinline__ void ldsm_x4(uint32_t* r, uint32_t addr) {
    asm volatile("ldmatrix.sync.aligned.m8n8.x4.shared.b16 {%0,%1,%2,%3}, [%4];"
                 : "=r"(r[0]), "=r"(r[1]), "=r"(r[2]), "=r"(r[3]) : "r"(addr));
}
template <int FP16>
__device__ __forceinline__ void mma_16816(float* c, const uint32_t* a,
                                          const uint32_t* b) {
    if (FP16)
        asm volatile(
            "mma.sync.aligned.m16n8k16.row.col.f32.f16.f16.f32 "
            "{%0,%1,%2,%3}, {%4,%5,%6,%7}, {%8,%9}, {%0,%1,%2,%3};"
            : "+f"(c[0]), "+f"(c[1]), "+f"(c[2]), "+f"(c[3])
            : "r"(a[0]), "r"(a[1]), "r"(a[2]), "r"(a[3]), "r"(b[0]), "r"(b[1]));
    else
        asm volatile(
            "mma.sync.aligned.m16n8k16.row.col.f32.bf16.bf16.f32 "
            "{%0,%1,%2,%3}, {%4,%5,%6,%7}, {%8,%9}, {%0,%1,%2,%3};"
            : "+f"(c[0]), "+f"(c[1]), "+f"(c[2]), "+f"(c[3])
            : "r"(a[0]), "r"(a[1]), "r"(a[2]), "r"(a[3]), "r"(b[0]), "r"(b[1]));
}

// ---------------- split/convert kernels -------------------------------------
// bf16 split-3: src fp32 [rows][512] -> dst bf16 [rows][1536]
// ISB=0 (A): [hi, hi, lo];  ISB=1 (B): [hi, lo, hi]
// REMAP=1: src row = (r&31)*SEQ + (r>>5)
template <int REMAP, int ISB>
__global__ __launch_bounds__(256) void split3_bf16_kernel(
    const float* __restrict__ src, __nv_bfloat16* __restrict__ dst, int rows)
{
    const int i = blockIdx.x * blockDim.x + threadIdx.x;
    if (i >= rows * 128) return;
    const int r = i >> 7;
    const int c4 = (i & 127) * 4;
    long srow;
    if (REMAP) srow = (long)((r & 31) * SEQ + (r >> 5)) * 512;
    else       srow = (long)r * 512;
    float4 v = *(const float4*)(src + srow + c4);
    __nv_bfloat16 h0 = __float2bfloat16(v.x), h1 = __float2bfloat16(v.y);
    __nv_bfloat16 h2 = __float2bfloat16(v.z), h3 = __float2bfloat16(v.w);
    __nv_bfloat16 l0 = __float2bfloat16(v.x - __bfloat162float(h0));
    __nv_bfloat16 l1 = __float2bfloat16(v.y - __bfloat162float(h1));
    __nv_bfloat16 l2 = __float2bfloat16(v.z - __bfloat162float(h2));
    __nv_bfloat16 l3 = __float2bfloat16(v.w - __bfloat162float(h3));
    __nv_bfloat162 hA(h0, h1), hB(h2, h3);
    __nv_bfloat162 lA(l0, l1), lB(l2, l3);
    __nv_bfloat16* d = dst + (long)r * K3 + c4;
    *(__nv_bfloat162*)(d + 0) = hA; *(__nv_bfloat162*)(d + 2) = hB;
    if (ISB) {
        *(__nv_bfloat162*)(d + 512)  = lA; *(__nv_bfloat162*)(d + 514)  = lB;
        *(__nv_bfloat162*)(d + 1024) = hA; *(__nv_bfloat162*)(d + 1026) = hB;
    } else {
        *(__nv_bfloat162*)(d + 512)  = hA; *(__nv_bfloat162*)(d + 514)  = hB;
        *(__nv_bfloat162*)(d + 1024) = lA; *(__nv_bfloat162*)(d + 1026) = lB;
    }
}

// plain fp32 -> fp16 convert (w_out), [rows][512]
__global__ __launch_bounds__(256) void cvt_fp16_kernel(
    const float* __restrict__ src, __half* __restrict__ dst, int rows)
{
    const int i = blockIdx.x * blockDim.x + threadIdx.x;
    if (i >= rows * 128) return;
    float4 v = ((const float4*)src)[i];
    __half2 a(__float2half(v.x), __float2half(v.y));
    __half2 b(__float2half(v.z), __float2half(v.w));
    ((__half2*)dst)[i * 2 + 0] = a;
    ((__half2*)dst)[i * 2 + 1] = b;
}

// ---------------- HMMA GEMM: C[M,N] = A'[M,KK] * B'[N,KK]^T -----------------
// CTA tile 128(M) x 256(N), 8 warps (2m x 4n), warp tile 64x64.
// K-step 64 (128B rows, XOR swizzle), 3-stage cp.async, 256 threads.
// MODE 0: +bias, C row = m.   MODE 1: no bias, C row = (m&31)*SEQ+(m>>5),
//         streaming stores (output not reused).
#define STGB ((128 + 256) * 128)       // 49152 per stage: A(128 rows) then B(256)
#define NSTG 3
#define SMEM_MMA (NSTG * STGB)         // 147456

template <int MODE, int KK, int FP16, typename T>
__global__ __launch_bounds__(256, 1) void mma_gemm_kernel(
    const T* __restrict__ A, const T* __restrict__ B,
    const float* __restrict__ bias, float* __restrict__ C, int N)
{
    extern __shared__ char smem[];
    const uint32_t sb = smem_u32(smem);
    const int tid  = threadIdx.x;
    const int wid  = tid >> 5, lane = tid & 31;
    const int m0   = blockIdx.x * 128;
    const int n0   = blockIdx.y * 256;
    const int wm   = wid & 1;            // 2 warps along m (64 each)
    const int wn   = wid >> 1;           // 4 warps along n (64 each)

    // ---- cp.async mapping: row = r8 (+32*i), col16 = c7
    const int r8 = tid >> 3;             // 0..31
    const int c7 = tid & 7;              // 0..7
    const uint32_t swc = (uint32_t)((c7 ^ (r8 & 7)) << 4);
    const T* gA = A + (long)(m0 + r8) * KK + c7 * 8;
    const T* gB = B + (long)(n0 + r8) * KK + c7 * 8;
    const uint32_t dA = sb + (uint32_t)(r8 * 128) + swc;
    const uint32_t dB = dA + 128 * 128;

#define LOAD_STAGE(slot, kt) do { \
        const uint32_t _o = (uint32_t)(slot) * STGB; \
        const long _k = (long)(kt) * 64; \
        _Pragma("unroll") \
        for (int _i = 0; _i < 4; _i++) \
            CP_ASYNC_16(dA + _o + _i * 32 * 128, gA + _k + (long)_i * 32 * KK); \
        _Pragma("unroll") \
        for (int _i = 0; _i < 8; _i++) \
            CP_ASYNC_16(dB + _o + _i * 32 * 128, gB + _k + (long)_i * 32 * KK); \
    } while (0)

    LOAD_STAGE(0, 0); CP_COMMIT();
    LOAD_STAGE(1, 1); CP_COMMIT();

    float acc[4][8][4];
#pragma unroll
    for (int i = 0; i < 4; i++)
#pragma unroll
        for (int j = 0; j < 8; j++)
#pragma unroll
            for (int k = 0; k < 4; k++) acc[i][j][k] = 0.f;

    // ldmatrix per-lane row offsets
    const uint32_t aRowB = (uint32_t)((wm * 64 + (lane & 15)) * 128);
    const uint32_t bRowB = (uint32_t)((wn * 64 + ((lane >> 4) << 3) + (lane & 7)) * 128);
    const uint32_t l7 = (uint32_t)(lane & 7);
    const uint32_t aC = (uint32_t)(lane >> 4);        // col16 half for A
    const uint32_t bC = (uint32_t)((lane >> 3) & 1);  // col16 half for B

    const int NKT = KK / 64;
    for (int kt = 0; kt < NKT; kt++) {
        CP_WAIT1();
        __syncthreads();
        const int ktn = kt + 2;
        if (ktn < NKT) LOAD_STAGE(ktn % 3, ktn);
        CP_COMMIT();

        const uint32_t Ab = sb + (uint32_t)(kt % 3) * STGB;
        const uint32_t Bb = Ab + 128 * 128;
#pragma unroll
        for (int kk = 0; kk < 4; kk++) {
            const uint32_t aSw = (((uint32_t)(kk * 2) + aC) ^ l7) << 4;
            const uint32_t bSw = (((uint32_t)(kk * 2) + bC) ^ l7) << 4;
            uint32_t af[4][4];
#pragma unroll
            for (int fm = 0; fm < 4; fm++)
                ldsm_x4(af[fm], Ab + aRowB + fm * 16 * 128 + aSw);
            uint32_t bf[4][4];
#pragma unroll
            for (int nb2 = 0; nb2 < 4; nb2++)
                ldsm_x4(bf[nb2], Bb + bRowB + nb2 * 16 * 128 + bSw);
#pragma unroll
            for (int fm = 0; fm < 4; fm++)
#pragma unroll
                for (int nb = 0; nb < 8; nb++)
                    mma_16816<FP16>(acc[fm][nb], af[fm],
                                    &bf[nb >> 1][(nb & 1) * 2]);
        }
    }
#undef LOAD_STAGE

    // ---- epilogue ----
    const int g = lane >> 2, t = lane & 3;
#pragma unroll
    for (int fm = 0; fm < 4; fm++) {
        const int m = m0 + wm * 64 + fm * 16 + g;
        long row0, row1;
        if (MODE == 1) {
            row0 = (long)((m & 31) * SEQ + (m >> 5)) * N;
            row1 = (long)(((m + 8) & 31) * SEQ + ((m + 8) >> 5)) * N;
        } else {
            row0 = (long)m * N;
            row1 = (long)(m + 8) * N;
        }
#pragma unroll
        for (int nb = 0; nb < 8; nb++) {
            const int n = n0 + wn * 64 + nb * 8 + t * 2;
            float2 v0, v1;
            v0.x = acc[fm][nb][0]; v0.y = acc[fm][nb][1];
            v1.x = acc[fm][nb][2]; v1.y = acc[fm][nb][3];
            if (MODE == 0) {
                const float b0 = bias[n], b1 = bias[n + 1];
                v0.x += b0; v0.y += b1;
                v1.x += b0; v1.y += b1;
                *(float2*)(C + row0 + n) = v0;
                *(float2*)(C + row1 + n) = v1;
            } else {
                __stcs((float2*)(C + row0 + n), v0);
                __stcs((float2*)(C + row1 + n), v1);
            }
        }
    }
}

// ---------------- persistent GRU recurrence kernel (R7 proven shape) -------
// Writes hs directly as fp16 (feeds only the logits GEMM).
__global__ __launch_bounds__(384) void gru_kernel(
    const float* __restrict__ hidden0,
    const float* __restrict__ w_hh,
    const float* __restrict__ b_hh)
{
    extern __shared__ float sm[];
    float* h_s  = sm;
    float* hg_s = sm + BATCH * HDIM;

    const int tid  = threadIdx.x;
    const int lane = tid & 31;
    const int w    = tid >> 5;
    const int u0   = blockIdx.x * 4;
    const int gate = w >> 2;
    const int jj   = w & 3;
    const int row  = gate * HDIM + u0 + jj;

    float wreg[16];
#pragma unroll
    for (int t = 0; t < 4; t++) {
        float4 wv = *(const float4*)(w_hh + (long)row * HDIM + 4 * lane + 128 * t);
        wreg[4 * t + 0] = wv.x; wreg[4 * t + 1] = wv.y;
        wreg[4 * t + 2] = wv.z; wreg[4 * t + 3] = wv.w;
    }
    const float bias = b_hh[row];
    const int nblocks = (int)gridDim.x;

    for (int s = 0; s < SEQ; s++) {
        for (int idx = tid; idx < (BATCH * HDIM) / 4; idx += 384) {
            float4 v;
            if (s == 0) v = ((const float4*)hidden0)[idx];
            else        v = __ldcg(((const float4*)g_h) + idx);
            *(float4*)&h_s[idx * 4] = v;
        }
        __syncthreads();

#pragma unroll 4
        for (int b = 0; b < BATCH; b++) {
            const float4* hp = (const float4*)&h_s[b * HDIM + 4 * lane];
            float s0 = 0.f, s1 = 0.f;
            {
                float4 h0 = hp[0],  h1 = hp[32], h2 = hp[64], h3 = hp[96];
                s0 += wreg[0] * h0.x + wreg[1] * h0.y + wreg[2] * h0.z + wreg[3] * h0.w;
                s1 += wreg[4] * h1.x + wreg[5] * h1.y + wreg[6] * h1.z + wreg[7] * h1.w;
                s0 += wreg[8] * h2.x + wreg[9] * h2.y + wreg[10] * h2.z + wreg[11] * h2.w;
                s1 += wreg[12] * h3.x + wreg[13] * h3.y + wreg[14] * h3.z + wreg[15] * h3.w;
            }
            float sum = s0 + s1;
#pragma unroll
            for (int off = 16; off; off >>= 1)
                sum += __shfl_xor_sync(0xffffffffu, sum, off);
            if (lane == 0) hg_s[w * BATCH + b] = sum + bias;
        }
        __syncthreads();

        if (tid < 128) {
            const int b = tid & 31;
            const int j = tid >> 5;
            const int u = u0 + j;
            const float* xg = g_xg + ((long)s * BATCH + b) * G3H;
            const float xr = xg[u], xz = xg[HDIM + u], xn = xg[2 * HDIM + u];
            const float hr = hg_s[(0 + j) * BATCH + b];
            const float hz = hg_s[(4 + j) * BATCH + b];
            const float hn = hg_s[(8 + j) * BATCH + b];
            const float r = 1.f / (1.f + expf(-(xr + hr)));
            const float z = 1.f / (1.f + expf(-(xz + hz)));
            const float n = tanhf(xn + r * hn);
            const float ho = h_s[b * HDIM + u];
            const float hnew = (1.f - z) * n + z * ho;
            __stcg(&g_h[b * HDIM + u], hnew);
            g_hs16[((long)s * BATCH + b) * HDIM + u] = __float2half(hnew);
        }

        __threadfence();
        __syncthreads();
        if (tid == 0) {
            atomicAdd(&g_arrive, 1);
            const int target = nblocks * (s + 1);
            while (*((volatile int*)&g_arrive) < target) { }
            __threadfence();
        }
        __syncthreads();
    }

    if (tid == 0) {
        const int v = atomicAdd(&g_exit, 1);
        if (v == nblocks - 1) {
            g_arrive = 0;
            g_exit = 0;
            __threadfence();
        }
    }
}

// ---------------- launcher --------------------------------------------------
extern "C" void kernel_launch(void* const* d_in, const int* in_sizes, int n_in,
                              void* d_out, int out_size)
{
    const float* embed_x = (const float*)d_in[0];
    const float* hidden  = (const float*)d_in[1];
    const float* w_ih    = (const float*)d_in[2];
    const float* w_hh    = (const float*)d_in[3];
    const float* b_ih    = (const float*)d_in[4];
    const float* b_hh    = (const float*)d_in[5];
    const float* w_out   = (const float*)d_in[6];
    float* out = (float*)d_out;

    void *xg_p = nullptr, *axg_p = nullptr, *bxg_p = nullptr;
    void *hs16_p = nullptr, *b16_p = nullptr;
    cudaGetSymbolAddress(&xg_p, g_xg);
    cudaGetSymbolAddress(&axg_p, g_axg);
    cudaGetSymbolAddress(&bxg_p, g_bxg);
    cudaGetSymbolAddress(&hs16_p, g_hs16);
    cudaGetSymbolAddress(&b16_p, g_b16);

    const int smem_gru = (BATCH * HDIM + 12 * BATCH) * (int)sizeof(float);
    cudaFuncSetAttribute(gru_kernel, cudaFuncAttributeMaxDynamicSharedMemorySize,
                         smem_gru);
    cudaFuncSetAttribute(mma_gemm_kernel<0, K3, 0, __nv_bfloat16>,
                         cudaFuncAttributeMaxDynamicSharedMemorySize, SMEM_MMA);
    cudaFuncSetAttribute(mma_gemm_kernel<1, HDIM, 1, __half>,
                         cudaFuncAttributeMaxDynamicSharedMemorySize, SMEM_MMA);

    const int M = SEQ * BATCH;   // 4096

    // 0) w_out -> fp16 (plain convert, K=512)
    cvt_fp16_kernel<<<(VDIM * 128) / 256, 256>>>(w_out, (__half*)b16_p, VDIM);

    // 1) expand embed_x -> bf16 A'_xg ; w_ih -> bf16 B'_xg
    split3_bf16_kernel<1, 0><<<(M * 128) / 256, 256>>>(embed_x,
        (__nv_bfloat16*)axg_p, M);
    split3_bf16_kernel<0, 1><<<(G3H * 128) / 256, 256>>>(w_ih,
        (__nv_bfloat16*)bxg_p, G3H);

    // 2) x_gates = embed_x @ w_ih^T + b_ih  (bf16 split-3)
    {
        dim3 grid(M / 128, G3H / 256);   // (32, 6)
        mma_gemm_kernel<0, K3, 0, __nv_bfloat16><<<grid, 256, SMEM_MMA>>>(
            (const __nv_bfloat16*)axg_p, (const __nv_bfloat16*)bxg_p,
            b_ih, (float*)xg_p, G3H);
    }

    // 3) GRU recurrence -> g_hs16 (fp16 A-side of logits)
    gru_kernel<<<128, 384, smem_gru>>>(hidden, w_hh, b_hh);

    // 4) logits = hs @ w_out^T -> out [b][s][v]  (plain fp16, K=512)
    {
        dim3 grid(M / 128, VDIM / 256);  // (32, 125)
        mma_gemm_kernel<1, HDIM, 1, __half><<<grid, 256, SMEM_MMA>>>(
            (const __half*)hs16_p, (const __half*)b16_p,
            nullptr, out, VDIM);
    }
}